// round 4
// baseline (speedup 1.0000x reference)
#include <cuda_runtime.h>

// Top-k threshold mask via sampled radix select, mask fused into the main
// pass. Order-preserving key: neg -> ~bits, pos -> bits|0x80000000 (matches
// XLA total order: -0 < +0, NaN last).

#define CAND_CAP  (1u << 24)
#define STAGE_CAP 2048
#define MARGIN    5000u
#define MAX_EXP   15

static __device__ unsigned g_hist64k[65536];   // sample hist / fallback hist
static __device__ unsigned g_hist2048[2048];   // level-1 candidate hist

static __device__ unsigned g_klo, g_khi, g_shift;
static __device__ float    g_flo, g_fhi;
static __device__ unsigned g_below;            // exact count of x < flo
static __device__ unsigned g_count;            // candidate count
static __device__ unsigned g_overflow;
static __device__ unsigned g_fail;
static __device__ float    g_threshold;
static __device__ unsigned g_cand[CAND_CAP];
static __device__ unsigned g_cidx[CAND_CAP];

__device__ __forceinline__ unsigned f2key(float f) {
    unsigned u = __float_as_uint(f);
    return (u & 0x80000000u) ? ~u : (u | 0x80000000u);
}
__device__ __forceinline__ float key2f(unsigned key) {
    unsigned u = (key & 0x80000000u) ? (key & 0x7fffffffu) : ~key;
    return __uint_as_float(u);
}

// ---------------- sampling: all 4 lanes of every 16th float4 ----------------
__global__ void k_sample(const float4* __restrict__ x4, int n4) {
    long long i = (long long)(blockIdx.x * blockDim.x + threadIdx.x) * 16;
    if (i < n4) {
        float4 v = __ldg(&x4[i]);
        atomicAdd(&g_hist64k[f2key(v.x) >> 16], 1u);
        atomicAdd(&g_hist64k[f2key(v.y) >> 16], 1u);
        atomicAdd(&g_hist64k[f2key(v.z) >> 16], 1u);
        atomicAdd(&g_hist64k[f2key(v.w) >> 16], 1u);
    }
}

// One block: locate the target quantile bin in the sample hist, expand by
// MARGIN samples per side (bounded), derive interval + float bounds + shift.
// Also resets per-replay counters and re-zeroes the sample hist.
__global__ void k_pick(unsigned t_target) {
    __shared__ unsigned s_part[1024];
    __shared__ int s_seg;
    __shared__ unsigned s_segexcl;
    int tid = threadIdx.x;
    if (tid == 0) s_seg = -1;
    if (tid == 1) { g_below = 0u; g_count = 0u; g_overflow = 0u; g_fail = 0u; }
    unsigned my = 0u;
    for (int b = tid * 64; b < tid * 64 + 64; b++) my += g_hist64k[b];
    s_part[tid] = my;
    __syncthreads();
    for (int off = 1; off < 1024; off <<= 1) {
        unsigned t = (tid >= off) ? s_part[tid - off] : 0u;
        __syncthreads();
        s_part[tid] += t;
        __syncthreads();
    }
    unsigned incl = s_part[tid], excl = incl - my;
    if (my && t_target >= excl && t_target < incl) { s_seg = tid; s_segexcl = excl; }
    __syncthreads();
    if (tid == 0) {
        if (s_seg < 0) {
            g_fail = 1u; g_klo = 1u; g_khi = 0u; g_shift = 0u;
            g_flo = 1.0f; g_fhi = 0.0f;
        } else {
            unsigned cum = s_segexcl;
            int bc = s_seg * 64;
            for (int b = s_seg * 64; b < s_seg * 64 + 64; b++) {
                unsigned c = g_hist64k[b];
                if (t_target >= cum && t_target < cum + c) { bc = b; break; }
                cum += c;
            }
            int lo = bc; unsigned accL = 0u;
            while (lo > 0 && accL < MARGIN && (bc - lo) < MAX_EXP) { lo--; accL += g_hist64k[lo]; }
            int hi = bc; unsigned accR = 0u;
            while (hi < 65535 && accR < MARGIN && (hi - bc) < MAX_EXP) { hi++; accR += g_hist64k[hi]; }
            if (lo == 0x8000) lo--;   // keep -0.0 strictly inside the interval
            if (hi == 0x7fff) hi++;   // keep +0.0 strictly inside the interval
            unsigned klo = (unsigned)lo << 16;
            unsigned khi = ((unsigned)hi << 16) | 0xffffu;
            unsigned range = khi - klo, sh = 0u;
            while ((range >> sh) >= 2048u) sh++;
            g_klo = klo; g_khi = khi; g_shift = sh;
            g_flo = key2f(klo); g_fhi = key2f(khi);
        }
    }
    __syncthreads();
    for (int b = tid; b < 65536; b += 1024) g_hist64k[b] = 0u;
}

// ---------------- main fused pass ----------------
// Reads x once, writes provisional mask (v > fhi), counts v < flo, stages
// (key, index) for interval candidates, builds level-1 candidate hist.
__global__ void k_main(const float4* __restrict__ x4, int n4,
                       float* __restrict__ out) {
    __shared__ unsigned s_key[STAGE_CAP];
    __shared__ unsigned s_idx[STAGE_CAP];
    __shared__ unsigned s_hist[2048];
    __shared__ unsigned s_cnt, s_below, s_base;
    for (int i = threadIdx.x; i < 2048; i += blockDim.x) s_hist[i] = 0u;
    if (threadIdx.x == 0) { s_cnt = 0u; s_below = 0u; }
    __syncthreads();
    const float flo = g_flo, fhi = g_fhi;
    const unsigned klo = g_klo;
    const unsigned sh = g_shift;
    const int lane = threadIdx.x & 31;
    const int stride = gridDim.x * blockDim.x;
    float4* o4 = (float4*)out;
    unsigned below = 0u;
#pragma unroll 4
    for (int i = blockIdx.x * blockDim.x + threadIdx.x; i < n4; i += stride) {
        float4 v = __ldcs(&x4[i]);
        float4 r;
        r.x = (v.x > fhi) ? 1.0f : 0.0f;
        r.y = (v.y > fhi) ? 1.0f : 0.0f;
        r.z = (v.z > fhi) ? 1.0f : 0.0f;
        r.w = (v.w > fhi) ? 1.0f : 0.0f;
        __stcs(&o4[i], r);
        below += (v.x < flo) + (v.y < flo) + (v.z < flo) + (v.w < flo);
        unsigned e = (unsigned)i * 4u;
        if (v.x >= flo && v.x <= fhi) {
            unsigned key = f2key(v.x);
            unsigned p = atomicAdd(&s_cnt, 1u);
            if (p < STAGE_CAP) { s_key[p] = key; s_idx[p] = e; atomicAdd(&s_hist[min((key - klo) >> sh, 2047u)], 1u); }
        }
        if (v.y >= flo && v.y <= fhi) {
            unsigned key = f2key(v.y);
            unsigned p = atomicAdd(&s_cnt, 1u);
            if (p < STAGE_CAP) { s_key[p] = key; s_idx[p] = e + 1u; atomicAdd(&s_hist[min((key - klo) >> sh, 2047u)], 1u); }
        }
        if (v.z >= flo && v.z <= fhi) {
            unsigned key = f2key(v.z);
            unsigned p = atomicAdd(&s_cnt, 1u);
            if (p < STAGE_CAP) { s_key[p] = key; s_idx[p] = e + 2u; atomicAdd(&s_hist[min((key - klo) >> sh, 2047u)], 1u); }
        }
        if (v.w >= flo && v.w <= fhi) {
            unsigned key = f2key(v.w);
            unsigned p = atomicAdd(&s_cnt, 1u);
            if (p < STAGE_CAP) { s_key[p] = key; s_idx[p] = e + 3u; atomicAdd(&s_hist[min((key - klo) >> sh, 2047u)], 1u); }
        }
    }
#pragma unroll
    for (int off = 16; off > 0; off >>= 1)
        below += __shfl_down_sync(0xffffffffu, below, off);
    if (lane == 0) atomicAdd(&s_below, below);
    __syncthreads();
    unsigned cnt = s_cnt < STAGE_CAP ? s_cnt : STAGE_CAP;
    if (threadIdx.x == 0) {
        if (s_cnt > STAGE_CAP) atomicExch(&g_overflow, 1u);
        atomicAdd(&g_below, s_below);
        s_base = atomicAdd(&g_count, cnt);
    }
    __syncthreads();
    unsigned base = s_base;
    for (unsigned i = threadIdx.x; i < cnt; i += blockDim.x) {
        g_cand[base + i] = s_key[i];
        g_cidx[base + i] = s_idx[i];
    }
    for (int i = threadIdx.x; i < 2048; i += blockDim.x)
        if (s_hist[i]) atomicAdd(&g_hist2048[i], s_hist[i]);
}

// scalar tail (launched only when n % 4 != 0)
__global__ void k_main_tail(const float* __restrict__ x, int n,
                            float* __restrict__ out) {
    int i = (n & ~3) + blockIdx.x * blockDim.x + threadIdx.x;
    if (i < n) {
        float v = x[i];
        out[i] = (v > g_fhi) ? 1.0f : 0.0f;
        if (v < g_flo) atomicAdd(&g_below, 1u);
        else if (v >= g_flo && v <= g_fhi) {
            unsigned key = f2key(v);
            unsigned p = atomicAdd(&g_count, 1u);
            if (p < CAND_CAP) {
                g_cand[p] = key; g_cidx[p] = (unsigned)i;
                atomicAdd(&g_hist2048[min((key - g_klo) >> g_shift, 2047u)], 1u);
            } else atomicExch(&g_overflow, 1u);
        }
    }
}

// ---------------- selection (single block, smem-staged scans) ----------------
__device__ __forceinline__ void warp_select_sm(const unsigned* hist, int nbins,
                                               unsigned target, unsigned* out_bin,
                                               unsigned* out_rank) {
    int lane = threadIdx.x & 31;
    unsigned run = 0u;
    for (int base = 0; base < nbins; base += 32) {
        unsigned c = hist[base + lane];
        unsigned v = c;
#pragma unroll
        for (int off = 1; off < 32; off <<= 1) {
            unsigned t = __shfl_up_sync(0xffffffffu, v, off);
            if (lane >= off) v += t;
        }
        unsigned incl = run + v, excl = incl - c;
        if (c && target >= excl && target < incl) { *out_bin = (unsigned)(base + lane); *out_rank = target - excl; }
        run += __shfl_sync(0xffffffffu, v, 31);
    }
}

__global__ void k_finish(unsigned idx) {
    __shared__ unsigned sh[2048];
    __shared__ unsigned s_bin, s_rank, s_target, s_ok, s_b2, s_w;
    int tid = threadIdx.x;
    // stage level-1 hist into smem and re-zero global copy for next replay
    for (int i = tid; i < 2048; i += blockDim.x) {
        sh[i] = g_hist2048[i];
        g_hist2048[i] = 0u;
    }
    if (tid == 0) {
        unsigned below = g_below, cnt = g_count;
        unsigned ok = (!g_overflow) && (!g_fail) && (idx >= below) &&
                      ((idx - below) < cnt) && (cnt <= CAND_CAP);
        if (!ok) g_fail = 1u;
        s_ok = ok; s_target = idx - below; s_bin = 0xffffffffu; s_rank = 0u;
    }
    __syncthreads();
    if (s_ok && tid < 32) warp_select_sm(sh, 2048, s_target, &s_bin, &s_rank);
    __syncthreads();
    if (tid == 0) {
        if (s_ok && s_bin == 0xffffffffu) { g_fail = 1u; s_ok = 0u; }
        if (s_ok) {
            s_b2 = g_klo + (s_bin << g_shift);
            unsigned w = 1u << g_shift;
            s_w = w;
        }
    }
    __syncthreads();
    if (!s_ok) return;
    // level-2: exact-key hist of candidates inside selected level-1 bin
    for (int i = tid; i < 2048; i += blockDim.x) sh[i] = 0u;
    __syncthreads();
    const unsigned b2 = s_b2, w = s_w;
    const unsigned nc = g_count;
    for (unsigned i = tid; i < nc; i += blockDim.x) {
        unsigned off = g_cand[i] - b2;
        if (off < w) atomicAdd(&sh[off], 1u);
    }
    __syncthreads();
    if (tid == 0) s_bin = 0xffffffffu;
    __syncthreads();
    if (tid < 32) {
        int nbins = (int)(w < 32u ? 32u : w);
        warp_select_sm(sh, nbins, s_rank, &s_bin, &s_rank);
    }
    __syncthreads();
    if (tid == 0) {
        if (s_bin == 0xffffffffu) g_fail = 1u;
        else g_threshold = key2f(b2 + s_bin);
    }
}

// Fixup: set mask=1 for candidates at/above threshold (others already 0).
__global__ void k_fixup(float* __restrict__ out) {
    if (g_fail) return;
    const float thr = g_threshold;
    const unsigned nc = g_count;
    const unsigned stride = gridDim.x * blockDim.x;
    for (unsigned i = blockIdx.x * blockDim.x + threadIdx.x; i < nc; i += stride) {
        if (key2f(g_cand[i]) >= thr) out[g_cidx[i]] = 1.0f;
    }
}

// ---------------- fallback: exact 2-pass 16-bit radix, one block ----------------
// Never taken on sane inputs (launch cost only). Correct for any input,
// including NaN/inf/degenerate distributions.
__global__ void f_all(const float* __restrict__ x, int n, unsigned idx) {
    if (!g_fail) return;
    __shared__ unsigned s_part[1024];
    __shared__ int s_seg;
    __shared__ unsigned s_segexcl, s_fb, s_fr;
    int tid = threadIdx.x;
    // pass 1: high 16 bits
    for (int i = tid; i < n; i += blockDim.x)
        atomicAdd(&g_hist64k[f2key(x[i]) >> 16], 1u);
    __syncthreads();
    for (int phase = 0; phase < 2; phase++) {
        unsigned target = (phase == 0) ? idx : s_fr;
        if (tid == 0) s_seg = -1;
        unsigned my = 0u;
        for (int b = tid * 64; b < tid * 64 + 64; b++) my += g_hist64k[b];
        s_part[tid] = my;
        __syncthreads();
        for (int off = 1; off < 1024; off <<= 1) {
            unsigned t = (tid >= off) ? s_part[tid - off] : 0u;
            __syncthreads();
            s_part[tid] += t;
            __syncthreads();
        }
        unsigned incl = s_part[tid], excl = incl - my;
        if (my && target >= excl && target < incl) { s_seg = tid; s_segexcl = excl; }
        __syncthreads();
        if (tid == 0 && s_seg >= 0) {
            unsigned cum = s_segexcl;
            for (int b = s_seg * 64; b < s_seg * 64 + 64; b++) {
                unsigned c = g_hist64k[b];
                if (target >= cum && target < cum + c) {
                    if (phase == 0) { s_fb = (unsigned)b; s_fr = target - cum; }
                    else g_threshold = key2f((s_fb << 16) | (unsigned)b);
                    break;
                }
                cum += c;
            }
        }
        __syncthreads();
        for (int b = tid; b < 65536; b += 1024) g_hist64k[b] = 0u;
        __syncthreads();
        if (phase == 0) {
            unsigned fb = s_fb;
            for (int i = tid; i < n; i += blockDim.x) {
                unsigned key = f2key(x[i]);
                if ((key >> 16) == fb) atomicAdd(&g_hist64k[key & 0xffffu], 1u);
            }
            __syncthreads();
        }
    }
}

__global__ void f_mask(const float* __restrict__ x, float* __restrict__ out, int n) {
    if (!g_fail) return;
    const float thr = g_threshold;
    const int stride = gridDim.x * blockDim.x;
    for (int i = blockIdx.x * blockDim.x + threadIdx.x; i < n; i += stride)
        out[i] = (x[i] >= thr) ? 1.0f : 0.0f;
}

__global__ void k_fill0(float* __restrict__ out, int n) {
    const int stride = gridDim.x * blockDim.x;
    for (int i = blockIdx.x * blockDim.x + threadIdx.x; i < n; i += stride)
        out[i] = 0.0f;
}

extern "C" void kernel_launch(void* const* d_in, const int* in_sizes, int n_in,
                              void* d_out, int out_size) {
    const float* x = (const float*)d_in[0];
    float* out = (float*)d_out;
    const long long n = (long long)in_sizes[0];
    const long long k = (long long)((double)n * 0.9);
    if (k <= 0) { k_fill0<<<1184, 256>>>(out, (int)n); return; }
    const unsigned idx = (unsigned)(n - k);   // 0-indexed ascending rank
    const int n4 = (int)(n >> 2);
    const long long s_n4 = (n4 + 15) / 16;    // sampled float4 count
    const long long m = s_n4 * 4;             // sampled value count
    unsigned t_target = (unsigned)((double)idx * (double)m / (double)n);
    if (t_target >= (unsigned)m) t_target = (unsigned)m - 1u;

    k_sample<<<(unsigned)((s_n4 + 255) / 256), 256>>>((const float4*)x, n4);
    k_pick<<<1, 1024>>>(t_target);
    k_main<<<1184, 256>>>((const float4*)x, n4, out);
    if (n & 3) k_main_tail<<<1, 64>>>(x, (int)n, out);
    k_finish<<<1, 1024>>>(idx);
    k_fixup<<<232, 256>>>(out);
    // fallback (no-ops unless g_fail)
    f_all<<<1, 1024>>>(x, (int)n, idx);
    f_mask<<<1184, 256>>>(x, out, (int)n);
}

// round 5
// speedup vs baseline: 1.7084x; 1.7084x over previous
#include <cuda_runtime.h>

// Top-k threshold mask via sampled radix select, mask fused into the main
// pass. Key map (order-preserving): neg -> ~bits, pos -> bits|0x80000000.

#define CAND_CAP  (1u << 24)
#define STAGE_CAP 2048
#define MARGIN    2500u
#define MAX_EXP   15

static __device__ unsigned g_hist64k[65536];   // sample hist / fallback hist
static __device__ unsigned g_hist2048[2048];   // level-1 candidate hist
static __device__ unsigned g_hist2b[2048];     // level-2 candidate hist

static __device__ unsigned g_klo, g_khi, g_shift;
static __device__ float    g_flo, g_fhi;
static __device__ unsigned g_below;            // exact count of x < flo
static __device__ unsigned g_count;            // candidate count
static __device__ unsigned g_overflow;
static __device__ unsigned g_fail;
static __device__ unsigned g_b2base, g_rank2;  // selected level-1 bin info
static __device__ float    g_threshold;
static __device__ unsigned g_cand[CAND_CAP];
static __device__ unsigned g_cidx[CAND_CAP];

__device__ __forceinline__ unsigned f2key(float f) {
    unsigned u = __float_as_uint(f);
    return (u & 0x80000000u) ? ~u : (u | 0x80000000u);
}
__device__ __forceinline__ float key2f(unsigned key) {
    unsigned u = (key & 0x80000000u) ? (key & 0x7fffffffu) : ~key;
    return __uint_as_float(u);
}

// ---------------- sampling: all 4 lanes of every 32nd float4 ----------------
__global__ void k_sample(const float4* __restrict__ x4, int n4) {
    long long i = (long long)(blockIdx.x * blockDim.x + threadIdx.x) * 32;
    if (i < n4) {
        float4 v = __ldg(&x4[i]);
        atomicAdd(&g_hist64k[f2key(v.x) >> 16], 1u);
        atomicAdd(&g_hist64k[f2key(v.y) >> 16], 1u);
        atomicAdd(&g_hist64k[f2key(v.z) >> 16], 1u);
        atomicAdd(&g_hist64k[f2key(v.w) >> 16], 1u);
    }
}

// One block: locate target quantile bin in sample hist, expand by MARGIN
// samples per side (bounded), derive interval/floats/shift. Resets per-replay
// state, zeroes the sample hist and both candidate hists.
__global__ void k_pick(unsigned t_target) {
    __shared__ unsigned s_part[1024];
    __shared__ int s_seg;
    __shared__ unsigned s_segexcl;
    int tid = threadIdx.x;
    if (tid == 0) s_seg = -1;
    if (tid == 1) { g_below = 0u; g_count = 0u; g_overflow = 0u; g_fail = 0u; }
    unsigned my = 0u;
    for (int b = tid * 64; b < tid * 64 + 64; b++) my += g_hist64k[b];
    s_part[tid] = my;
    __syncthreads();
    for (int off = 1; off < 1024; off <<= 1) {
        unsigned t = (tid >= off) ? s_part[tid - off] : 0u;
        __syncthreads();
        s_part[tid] += t;
        __syncthreads();
    }
    unsigned incl = s_part[tid], excl = incl - my;
    if (my && t_target >= excl && t_target < incl) { s_seg = tid; s_segexcl = excl; }
    __syncthreads();
    if (tid == 0) {
        if (s_seg < 0) {
            g_fail = 1u; g_klo = 1u; g_khi = 0u; g_shift = 0u;
            g_flo = 1.0f; g_fhi = 0.0f;
        } else {
            unsigned cum = s_segexcl;
            int bc = s_seg * 64;
            for (int b = s_seg * 64; b < s_seg * 64 + 64; b++) {
                unsigned c = g_hist64k[b];
                if (t_target >= cum && t_target < cum + c) { bc = b; break; }
                cum += c;
            }
            int lo = bc; unsigned accL = 0u;
            while (lo > 0 && accL < MARGIN && (bc - lo) < MAX_EXP) { lo--; accL += g_hist64k[lo]; }
            int hi = bc; unsigned accR = 0u;
            while (hi < 65535 && accR < MARGIN && (hi - bc) < MAX_EXP) { hi++; accR += g_hist64k[hi]; }
            if (lo == 0x8000) lo--;   // keep -0.0 strictly inside the interval
            if (hi == 0x7fff) hi++;   // keep +0.0 strictly inside the interval
            unsigned klo = (unsigned)lo << 16;
            unsigned khi = ((unsigned)hi << 16) | 0xffffu;
            unsigned range = khi - klo, sh = 0u;
            while ((range >> sh) >= 2048u) sh++;
            g_klo = klo; g_khi = khi; g_shift = sh;
            g_flo = key2f(klo); g_fhi = key2f(khi);
        }
    }
    __syncthreads();
    for (int b = tid; b < 65536; b += 1024) g_hist64k[b] = 0u;
    for (int b = tid; b < 2048; b += 1024) { g_hist2048[b] = 0u; g_hist2b[b] = 0u; }
}

// ---------------- main fused pass ----------------
// Reads x once, writes provisional mask (v > fhi), counts v < flo, stages
// (key, index) for interval candidates, builds level-1 candidate hist.
__global__ void k_main(const float4* __restrict__ x4, int n4,
                       float* __restrict__ out) {
    __shared__ unsigned s_key[STAGE_CAP];
    __shared__ unsigned s_idx[STAGE_CAP];
    __shared__ unsigned s_hist[2048];
    __shared__ unsigned s_cnt, s_below, s_base;
    for (int i = threadIdx.x; i < 2048; i += blockDim.x) s_hist[i] = 0u;
    if (threadIdx.x == 0) { s_cnt = 0u; s_below = 0u; }
    __syncthreads();
    const float flo = g_flo, fhi = g_fhi;
    const unsigned klo = g_klo;
    const unsigned sh = g_shift;
    const int lane = threadIdx.x & 31;
    const int stride = gridDim.x * blockDim.x;
    float4* o4 = (float4*)out;
    unsigned below = 0u;
#pragma unroll 4
    for (int i = blockIdx.x * blockDim.x + threadIdx.x; i < n4; i += stride) {
        float4 v = __ldcs(&x4[i]);
        float4 r;
        r.x = (v.x > fhi) ? 1.0f : 0.0f;
        r.y = (v.y > fhi) ? 1.0f : 0.0f;
        r.z = (v.z > fhi) ? 1.0f : 0.0f;
        r.w = (v.w > fhi) ? 1.0f : 0.0f;
        __stcs(&o4[i], r);
        below += (v.x < flo) + (v.y < flo) + (v.z < flo) + (v.w < flo);
        unsigned e = (unsigned)i * 4u;
        if (v.x >= flo && v.x <= fhi) {
            unsigned key = f2key(v.x);
            unsigned p = atomicAdd(&s_cnt, 1u);
            if (p < STAGE_CAP) { s_key[p] = key; s_idx[p] = e; atomicAdd(&s_hist[min((key - klo) >> sh, 2047u)], 1u); }
        }
        if (v.y >= flo && v.y <= fhi) {
            unsigned key = f2key(v.y);
            unsigned p = atomicAdd(&s_cnt, 1u);
            if (p < STAGE_CAP) { s_key[p] = key; s_idx[p] = e + 1u; atomicAdd(&s_hist[min((key - klo) >> sh, 2047u)], 1u); }
        }
        if (v.z >= flo && v.z <= fhi) {
            unsigned key = f2key(v.z);
            unsigned p = atomicAdd(&s_cnt, 1u);
            if (p < STAGE_CAP) { s_key[p] = key; s_idx[p] = e + 2u; atomicAdd(&s_hist[min((key - klo) >> sh, 2047u)], 1u); }
        }
        if (v.w >= flo && v.w <= fhi) {
            unsigned key = f2key(v.w);
            unsigned p = atomicAdd(&s_cnt, 1u);
            if (p < STAGE_CAP) { s_key[p] = key; s_idx[p] = e + 3u; atomicAdd(&s_hist[min((key - klo) >> sh, 2047u)], 1u); }
        }
    }
#pragma unroll
    for (int off = 16; off > 0; off >>= 1)
        below += __shfl_down_sync(0xffffffffu, below, off);
    if (lane == 0) atomicAdd(&s_below, below);
    __syncthreads();
    unsigned cnt = s_cnt < STAGE_CAP ? s_cnt : STAGE_CAP;
    if (threadIdx.x == 0) {
        if (s_cnt > STAGE_CAP) atomicExch(&g_overflow, 1u);
        atomicAdd(&g_below, s_below);
        s_base = atomicAdd(&g_count, cnt);
    }
    __syncthreads();
    unsigned base = s_base;
    for (unsigned i = threadIdx.x; i < cnt; i += blockDim.x) {
        g_cand[base + i] = s_key[i];
        g_cidx[base + i] = s_idx[i];
    }
    for (int i = threadIdx.x; i < 2048; i += blockDim.x)
        if (s_hist[i]) atomicAdd(&g_hist2048[i], s_hist[i]);
}

// scalar tail (launched only when n % 4 != 0)
__global__ void k_main_tail(const float* __restrict__ x, int n,
                            float* __restrict__ out) {
    int i = (n & ~3) + blockIdx.x * blockDim.x + threadIdx.x;
    if (i < n) {
        float v = x[i];
        out[i] = (v > g_fhi) ? 1.0f : 0.0f;
        if (v < g_flo) atomicAdd(&g_below, 1u);
        else if (v >= g_flo && v <= g_fhi) {
            unsigned key = f2key(v);
            unsigned p = atomicAdd(&g_count, 1u);
            if (p < CAND_CAP) {
                g_cand[p] = key; g_cidx[p] = (unsigned)i;
                atomicAdd(&g_hist2048[min((key - g_klo) >> g_shift, 2047u)], 1u);
            } else atomicExch(&g_overflow, 1u);
        }
    }
}

// ---------------- selection helpers ----------------
__device__ __forceinline__ void warp_select_sm(const unsigned* hist, int nbins,
                                               unsigned target, unsigned* out_bin,
                                               unsigned* out_rank) {
    int lane = threadIdx.x & 31;
    unsigned run = 0u;
    for (int base = 0; base < nbins; base += 32) {
        unsigned c = hist[base + lane];
        unsigned v = c;
#pragma unroll
        for (int off = 1; off < 32; off <<= 1) {
            unsigned t = __shfl_up_sync(0xffffffffu, v, off);
            if (lane >= off) v += t;
        }
        unsigned incl = run + v, excl = incl - c;
        if (c && target >= excl && target < incl) { *out_bin = (unsigned)(base + lane); *out_rank = target - excl; }
        run += __shfl_sync(0xffffffffu, v, 31);
    }
}

// Level-2 pass (multi-block): every block redoes the cheap smem level-1 scan
// (deterministic, identical result), then histograms candidates falling in the
// selected level-1 bin. Block 0 publishes (b2base, rank2) / fail.
__global__ void k_sel2(unsigned idx) {
    __shared__ unsigned sh[2048];
    __shared__ unsigned s_bin, s_rank, s_ok;
    int tid = threadIdx.x;
    for (int i = tid; i < 2048; i += blockDim.x) sh[i] = g_hist2048[i];
    if (tid == 0) {
        unsigned below = g_below, cnt = g_count;
        s_ok = (!g_overflow) && (!g_fail) && (idx >= below) &&
               ((idx - below) < cnt) && (cnt <= CAND_CAP);
        s_bin = 0xffffffffu; s_rank = 0u;
    }
    __syncthreads();
    if (s_ok && tid < 32) warp_select_sm(sh, 2048, idx - g_below, &s_bin, &s_rank);
    __syncthreads();
    if (tid == 0) {
        if (s_ok && s_bin == 0xffffffffu) s_ok = 0u;
        if (!s_ok && blockIdx.x == 0) g_fail = 1u;
        if (s_ok && blockIdx.x == 0) {
            g_b2base = g_klo + (s_bin << g_shift);
            g_rank2 = s_rank;
        }
    }
    __syncthreads();
    if (!s_ok) return;
    const unsigned b2 = g_klo + (s_bin << g_shift);
    const unsigned w = 1u << g_shift;
    // reuse sh as the level-2 hist
    for (int i = tid; i < 2048; i += blockDim.x) sh[i] = 0u;
    __syncthreads();
    const unsigned nc = g_count;
    const unsigned stride = gridDim.x * blockDim.x;
    for (unsigned i = blockIdx.x * blockDim.x + threadIdx.x; i < nc; i += stride) {
        unsigned off = g_cand[i] - b2;
        if (off < w) atomicAdd(&sh[off], 1u);
    }
    __syncthreads();
    unsigned wcap = w < 2048u ? w : 2048u;
    for (unsigned i = tid; i < wcap; i += blockDim.x)
        if (sh[i]) atomicAdd(&g_hist2b[i], sh[i]);
}

// Fixup (multi-block): every block redoes the smem level-2 scan to get the
// threshold, then sets mask=1 for candidates >= threshold.
__global__ void k_fixup(float* __restrict__ out) {
    __shared__ unsigned sh[2048];
    __shared__ unsigned s_bin, s_rank;
    __shared__ float s_thr;
    int tid = threadIdx.x;
    if (g_fail) return;
    for (int i = tid; i < 2048; i += blockDim.x) sh[i] = g_hist2b[i];
    if (tid == 0) { s_bin = 0xffffffffu; s_rank = 0u; }
    __syncthreads();
    const unsigned w = 1u << g_shift;
    if (tid < 32) {
        int nbins = (int)(w < 32u ? 32u : (w > 2048u ? 2048u : w));
        warp_select_sm(sh, nbins, g_rank2, &s_bin, &s_rank);
    }
    __syncthreads();
    if (tid == 0) {
        if (s_bin == 0xffffffffu) {
            if (blockIdx.x == 0) g_fail = 1u;
            s_thr = __int_as_float(0x7f800000);  // +inf -> no fixup writes
        } else {
            float thr = key2f(g_b2base + s_bin);
            s_thr = thr;
            if (blockIdx.x == 0) g_threshold = thr;
        }
    }
    __syncthreads();
    const float thr = s_thr;
    const unsigned nc = g_count;
    const unsigned stride = gridDim.x * blockDim.x;
    for (unsigned i = blockIdx.x * blockDim.x + threadIdx.x; i < nc; i += stride) {
        if (key2f(g_cand[i]) >= thr) out[g_cidx[i]] = 1.0f;
    }
}

// ---------------- fallback: exact 2-pass 16-bit radix, one block ----------------
// Never taken on sane inputs (launch cost only); correct for any input.
__global__ void f_all(const float* __restrict__ x, int n, unsigned idx) {
    if (!g_fail) return;
    __shared__ unsigned s_part[1024];
    __shared__ int s_seg;
    __shared__ unsigned s_segexcl, s_fb, s_fr;
    int tid = threadIdx.x;
    for (int b = tid; b < 65536; b += 1024) g_hist64k[b] = 0u;
    __syncthreads();
    for (int i = tid; i < n; i += blockDim.x)
        atomicAdd(&g_hist64k[f2key(x[i]) >> 16], 1u);
    __syncthreads();
    for (int phase = 0; phase < 2; phase++) {
        unsigned target = (phase == 0) ? idx : s_fr;
        if (tid == 0) s_seg = -1;
        unsigned my = 0u;
        for (int b = tid * 64; b < tid * 64 + 64; b++) my += g_hist64k[b];
        s_part[tid] = my;
        __syncthreads();
        for (int off = 1; off < 1024; off <<= 1) {
            unsigned t = (tid >= off) ? s_part[tid - off] : 0u;
            __syncthreads();
            s_part[tid] += t;
            __syncthreads();
        }
        unsigned incl = s_part[tid], excl = incl - my;
        if (my && target >= excl && target < incl) { s_seg = tid; s_segexcl = excl; }
        __syncthreads();
        if (tid == 0 && s_seg >= 0) {
            unsigned cum = s_segexcl;
            for (int b = s_seg * 64; b < s_seg * 64 + 64; b++) {
                unsigned c = g_hist64k[b];
                if (target >= cum && target < cum + c) {
                    if (phase == 0) { s_fb = (unsigned)b; s_fr = target - cum; }
                    else g_threshold = key2f((s_fb << 16) | (unsigned)b);
                    break;
                }
                cum += c;
            }
        }
        __syncthreads();
        for (int b = tid; b < 65536; b += 1024) g_hist64k[b] = 0u;
        __syncthreads();
        if (phase == 0) {
            unsigned fb = s_fb;
            for (int i = tid; i < n; i += blockDim.x) {
                unsigned key = f2key(x[i]);
                if ((key >> 16) == fb) atomicAdd(&g_hist64k[key & 0xffffu], 1u);
            }
            __syncthreads();
        }
    }
}

__global__ void f_mask(const float* __restrict__ x, float* __restrict__ out, int n) {
    if (!g_fail) return;
    const float thr = g_threshold;
    const int stride = gridDim.x * blockDim.x;
    for (int i = blockIdx.x * blockDim.x + threadIdx.x; i < n; i += stride)
        out[i] = (x[i] >= thr) ? 1.0f : 0.0f;
}

__global__ void k_fill0(float* __restrict__ out, int n) {
    const int stride = gridDim.x * blockDim.x;
    for (int i = blockIdx.x * blockDim.x + threadIdx.x; i < n; i += stride)
        out[i] = 0.0f;
}

extern "C" void kernel_launch(void* const* d_in, const int* in_sizes, int n_in,
                              void* d_out, int out_size) {
    const float* x = (const float*)d_in[0];
    float* out = (float*)d_out;
    const long long n = (long long)in_sizes[0];
    const long long k = (long long)((double)n * 0.9);
    if (k <= 0) { k_fill0<<<1184, 256>>>(out, (int)n); return; }
    const unsigned idx = (unsigned)(n - k);   // 0-indexed ascending rank
    const int n4 = (int)(n >> 2);
    const long long s_n4 = (n4 + 31) / 32;    // sampled float4 count
    const long long m = s_n4 * 4;             // sampled value count
    unsigned t_target = (unsigned)((double)idx * (double)m / (double)n);
    if (t_target >= (unsigned)m) t_target = (unsigned)m - 1u;

    k_sample<<<(unsigned)((s_n4 + 255) / 256), 256>>>((const float4*)x, n4);
    k_pick<<<1, 1024>>>(t_target);
    k_main<<<1184, 256>>>((const float4*)x, n4, out);
    if (n & 3) k_main_tail<<<1, 64>>>(x, (int)n, out);
    k_sel2<<<296, 256>>>(idx);
    k_fixup<<<296, 256>>>(out);
    // fallback (no-ops unless g_fail)
    f_all<<<1, 1024>>>(x, (int)n, idx);
    f_mask<<<1184, 256>>>(x, out, (int)n);
}

// round 6
// speedup vs baseline: 1.7716x; 1.0370x over previous
#include <cuda_runtime.h>

// Top-k threshold mask via sampled radix select, mask fused into the main
// pass. Key map (order-preserving): neg -> ~bits, pos -> bits|0x80000000.

#define CAND_CAP  (1u << 24)
#define STAGE_CAP 2048
#define MARGIN    2500u
#define MAX_EXP   15

static __device__ unsigned g_hist64k[65536];   // sample hist / fallback hist
static __device__ unsigned g_hist2048[2048];   // level-1 candidate hist
static __device__ unsigned g_hist2b[2048];     // level-2 candidate hist

static __device__ unsigned g_klo, g_khi, g_shift;
static __device__ float    g_flo, g_fhi;
static __device__ unsigned g_below;            // exact count of x < flo
static __device__ unsigned g_count;            // candidate count
static __device__ unsigned g_overflow;
static __device__ unsigned g_fail;
static __device__ unsigned g_b2base, g_rank2;  // selected level-1 bin info
static __device__ float    g_threshold;
static __device__ unsigned g_cand[CAND_CAP];
static __device__ unsigned g_cidx[CAND_CAP];

__device__ __forceinline__ unsigned f2key(float f) {
    unsigned u = __float_as_uint(f);
    return (u & 0x80000000u) ? ~u : (u | 0x80000000u);
}
__device__ __forceinline__ float key2f(unsigned key) {
    unsigned u = (key & 0x80000000u) ? (key & 0x7fffffffu) : ~key;
    return __uint_as_float(u);
}

// ---------------- sampling: first 32 float4s of every 1024-float4 chunk ----
// Same 1/32 rate as before but fully coalesced (whole 128B lines used).
__global__ void k_sample(const float4* __restrict__ x4, int n4) {
    int t = blockIdx.x * blockDim.x + threadIdx.x;
    long long i = (long long)(t >> 5) * 1024 + (t & 31);
    if (i < n4) {
        float4 v = __ldg(&x4[i]);
        atomicAdd(&g_hist64k[f2key(v.x) >> 16], 1u);
        atomicAdd(&g_hist64k[f2key(v.y) >> 16], 1u);
        atomicAdd(&g_hist64k[f2key(v.z) >> 16], 1u);
        atomicAdd(&g_hist64k[f2key(v.w) >> 16], 1u);
    }
}

// One block, 1024 threads: locate target quantile bin of the sample hist,
// expand by MARGIN samples per side (bounded by MAX_EXP bins), derive
// interval + float bounds + shift. The expansion walk reads a smem-staged
// window only (no serial global loads). Resets all per-replay state.
__global__ void k_pick(unsigned t_target) {
    __shared__ unsigned s_part[1024];
    __shared__ unsigned s_win[192];
    __shared__ int s_seg;
    __shared__ unsigned s_segexcl;
    int tid = threadIdx.x;
    if (tid == 0) s_seg = -1;
    if (tid == 1) { g_below = 0u; g_count = 0u; g_overflow = 0u; g_fail = 0u; }
    unsigned my = 0u;
    for (int b = tid * 64; b < tid * 64 + 64; b++) my += g_hist64k[b];
    s_part[tid] = my;
    __syncthreads();
    for (int off = 1; off < 1024; off <<= 1) {
        unsigned t = (tid >= off) ? s_part[tid - off] : 0u;
        __syncthreads();
        s_part[tid] += t;
        __syncthreads();
    }
    unsigned incl = s_part[tid], excl = incl - my;
    if (my && t_target >= excl && t_target < incl) { s_seg = tid; s_segexcl = excl; }
    __syncthreads();
    int seg = s_seg;
    int w0 = seg * 64 - 64;               // window base (may be negative)
    if (seg >= 0) {
        for (int j = tid; j < 192; j += 1024) {
            int b = w0 + j;
            s_win[j] = (b >= 0 && b < 65536) ? g_hist64k[b] : 0u;
        }
    }
    __syncthreads();
    if (tid == 0) {
        if (seg < 0) {
            g_fail = 1u; g_klo = 1u; g_khi = 0u; g_shift = 0u;
            g_flo = 1.0f; g_fhi = 0.0f;
        } else {
            unsigned cum = s_segexcl;
            int bcw = 64;
            for (int j = 64; j < 128; j++) {
                unsigned c = s_win[j];
                if (t_target >= cum && t_target < cum + c) { bcw = j; break; }
                cum += c;
            }
            int lo = bcw; unsigned accL = 0u;
            while ((w0 + lo) > 0 && accL < MARGIN && (bcw - lo) < MAX_EXP) { lo--; accL += s_win[lo]; }
            int hi = bcw; unsigned accR = 0u;
            while ((w0 + hi) < 65535 && accR < MARGIN && (hi - bcw) < MAX_EXP) { hi++; accR += s_win[hi]; }
            int lob = w0 + lo, hib = w0 + hi;
            if (lob == 0x8000) lob--;   // keep -0.0 strictly inside
            if (hib == 0x7fff) hib++;   // keep +0.0 strictly inside
            if (lob < 0) lob = 0;
            if (hib > 65535) hib = 65535;
            unsigned klo = (unsigned)lob << 16;
            unsigned khi = ((unsigned)hib << 16) | 0xffffu;
            unsigned range = khi - klo, sh = 0u;
            while ((range >> sh) >= 2048u) sh++;
            g_klo = klo; g_khi = khi; g_shift = sh;
            g_flo = key2f(klo); g_fhi = key2f(khi);
        }
    }
    __syncthreads();
    for (int b = tid; b < 65536; b += 1024) g_hist64k[b] = 0u;
    for (int b = tid; b < 2048; b += 1024) { g_hist2048[b] = 0u; g_hist2b[b] = 0u; }
}

// ---------------- main fused pass ----------------
// Reads x once, writes provisional mask (v > fhi), counts v < flo, stages
// (key, index) for interval candidates, builds level-1 candidate hist.
__global__ void k_main(const float4* __restrict__ x4, int n4,
                       float* __restrict__ out) {
    __shared__ unsigned s_key[STAGE_CAP];
    __shared__ unsigned s_idx[STAGE_CAP];
    __shared__ unsigned s_hist[2048];
    __shared__ unsigned s_cnt, s_below, s_base;
    for (int i = threadIdx.x; i < 2048; i += blockDim.x) s_hist[i] = 0u;
    if (threadIdx.x == 0) { s_cnt = 0u; s_below = 0u; }
    __syncthreads();
    const float flo = g_flo, fhi = g_fhi;
    const unsigned klo = g_klo;
    const unsigned sh = g_shift;
    const int lane = threadIdx.x & 31;
    const int stride = gridDim.x * blockDim.x;
    float4* o4 = (float4*)out;
    unsigned below = 0u;
#pragma unroll 4
    for (int i = blockIdx.x * blockDim.x + threadIdx.x; i < n4; i += stride) {
        float4 v = __ldcs(&x4[i]);
        float4 r;
        r.x = (v.x > fhi) ? 1.0f : 0.0f;
        r.y = (v.y > fhi) ? 1.0f : 0.0f;
        r.z = (v.z > fhi) ? 1.0f : 0.0f;
        r.w = (v.w > fhi) ? 1.0f : 0.0f;
        __stcs(&o4[i], r);
        below += (v.x < flo) + (v.y < flo) + (v.z < flo) + (v.w < flo);
        unsigned e = (unsigned)i * 4u;
        if (v.x >= flo && v.x <= fhi) {
            unsigned key = f2key(v.x);
            unsigned p = atomicAdd(&s_cnt, 1u);
            if (p < STAGE_CAP) { s_key[p] = key; s_idx[p] = e; atomicAdd(&s_hist[min((key - klo) >> sh, 2047u)], 1u); }
        }
        if (v.y >= flo && v.y <= fhi) {
            unsigned key = f2key(v.y);
            unsigned p = atomicAdd(&s_cnt, 1u);
            if (p < STAGE_CAP) { s_key[p] = key; s_idx[p] = e + 1u; atomicAdd(&s_hist[min((key - klo) >> sh, 2047u)], 1u); }
        }
        if (v.z >= flo && v.z <= fhi) {
            unsigned key = f2key(v.z);
            unsigned p = atomicAdd(&s_cnt, 1u);
            if (p < STAGE_CAP) { s_key[p] = key; s_idx[p] = e + 2u; atomicAdd(&s_hist[min((key - klo) >> sh, 2047u)], 1u); }
        }
        if (v.w >= flo && v.w <= fhi) {
            unsigned key = f2key(v.w);
            unsigned p = atomicAdd(&s_cnt, 1u);
            if (p < STAGE_CAP) { s_key[p] = key; s_idx[p] = e + 3u; atomicAdd(&s_hist[min((key - klo) >> sh, 2047u)], 1u); }
        }
    }
#pragma unroll
    for (int off = 16; off > 0; off >>= 1)
        below += __shfl_down_sync(0xffffffffu, below, off);
    if (lane == 0) atomicAdd(&s_below, below);
    __syncthreads();
    unsigned cnt = s_cnt < STAGE_CAP ? s_cnt : STAGE_CAP;
    if (threadIdx.x == 0) {
        if (s_cnt > STAGE_CAP) atomicExch(&g_overflow, 1u);
        atomicAdd(&g_below, s_below);
        s_base = atomicAdd(&g_count, cnt);
    }
    __syncthreads();
    unsigned base = s_base;
    for (unsigned i = threadIdx.x; i < cnt; i += blockDim.x) {
        g_cand[base + i] = s_key[i];
        g_cidx[base + i] = s_idx[i];
    }
    for (int i = threadIdx.x; i < 2048; i += blockDim.x)
        if (s_hist[i]) atomicAdd(&g_hist2048[i], s_hist[i]);
}

// scalar tail (launched only when n % 4 != 0)
__global__ void k_main_tail(const float* __restrict__ x, int n,
                            float* __restrict__ out) {
    int i = (n & ~3) + blockIdx.x * blockDim.x + threadIdx.x;
    if (i < n) {
        float v = x[i];
        out[i] = (v > g_fhi) ? 1.0f : 0.0f;
        if (v < g_flo) atomicAdd(&g_below, 1u);
        else if (v >= g_flo && v <= g_fhi) {
            unsigned key = f2key(v);
            unsigned p = atomicAdd(&g_count, 1u);
            if (p < CAND_CAP) {
                g_cand[p] = key; g_cidx[p] = (unsigned)i;
                atomicAdd(&g_hist2048[min((key - g_klo) >> g_shift, 2047u)], 1u);
            } else atomicExch(&g_overflow, 1u);
        }
    }
}

// ---------------- block-parallel select over a 2048-bin smem hist ----------
// blockDim must be 256. Exactly one thread writes *out_bin/*out_rank if the
// target rank falls inside the histogram; caller pre-inits out_bin=~0u and
// wraps with __syncthreads().
__device__ __forceinline__ void block_select2048(const unsigned* hist,
                                                 unsigned target,
                                                 unsigned* out_bin,
                                                 unsigned* out_rank) {
    __shared__ unsigned s_wofs[9];
    int tid = threadIdx.x, lane = tid & 31, wid = tid >> 5;
    unsigned base = (unsigned)tid * 8u;
    unsigned my = 0u;
#pragma unroll
    for (int j = 0; j < 8; j++) my += hist[base + j];
    unsigned v = my;
#pragma unroll
    for (int off = 1; off < 32; off <<= 1) {
        unsigned t = __shfl_up_sync(0xffffffffu, v, off);
        if (lane >= off) v += t;
    }
    if (lane == 31) s_wofs[wid + 1] = v;
    if (tid == 0) s_wofs[0] = 0u;
    __syncthreads();
    if (tid == 0)
        for (int w = 1; w <= 8; w++) s_wofs[w] += s_wofs[w - 1];
    __syncthreads();
    unsigned excl = s_wofs[wid] + v - my;
    if (my && target >= excl && target < excl + my) {
        unsigned cum = excl;
#pragma unroll
        for (int j = 0; j < 8; j++) {
            unsigned c = hist[base + j];
            if (target < cum + c) { *out_bin = base + (unsigned)j; *out_rank = target - cum; break; }
            cum += c;
        }
    }
    __syncthreads();
}

// Level-2 pass (multi-block, 256 thr): every block redoes the cheap level-1
// block-select (deterministic), then histograms candidates inside the
// selected level-1 bin. Block 0 publishes (b2base, rank2) / fail.
__global__ void k_sel2(unsigned idx) {
    __shared__ unsigned sh[2048];
    __shared__ unsigned s_bin, s_rank, s_ok;
    int tid = threadIdx.x;
    for (int i = tid; i < 2048; i += blockDim.x) sh[i] = g_hist2048[i];
    if (tid == 0) {
        unsigned below = g_below, cnt = g_count;
        s_ok = (!g_overflow) && (!g_fail) && (idx >= below) &&
               ((idx - below) < cnt) && (cnt <= CAND_CAP);
        s_bin = 0xffffffffu; s_rank = 0u;
    }
    __syncthreads();
    if (s_ok) block_select2048(sh, idx - g_below, &s_bin, &s_rank);
    else __syncthreads(), __syncthreads();  // keep barrier counts trivially safe
    __syncthreads();
    if (tid == 0) {
        if (s_ok && s_bin == 0xffffffffu) s_ok = 0u;
        if (!s_ok && blockIdx.x == 0) g_fail = 1u;
        if (s_ok && blockIdx.x == 0) {
            g_b2base = g_klo + (s_bin << g_shift);
            g_rank2 = s_rank;
        }
    }
    __syncthreads();
    if (!s_ok) return;
    const unsigned b2 = g_klo + (s_bin << g_shift);
    const unsigned w = 1u << g_shift;
    for (int i = tid; i < 2048; i += blockDim.x) sh[i] = 0u;
    __syncthreads();
    const unsigned nc = g_count;
    const unsigned stride = gridDim.x * blockDim.x;
    for (unsigned i = blockIdx.x * blockDim.x + threadIdx.x; i < nc; i += stride) {
        unsigned off = g_cand[i] - b2;
        if (off < w) atomicAdd(&sh[off], 1u);
    }
    __syncthreads();
    unsigned wcap = w < 2048u ? w : 2048u;
    for (unsigned i = tid; i < wcap; i += blockDim.x)
        if (sh[i]) atomicAdd(&g_hist2b[i], sh[i]);
}

// Fixup (multi-block, 256 thr): every block redoes the level-2 block-select
// to get the exact threshold, then sets mask=1 for candidates >= threshold.
__global__ void k_fixup(float* __restrict__ out) {
    __shared__ unsigned sh[2048];
    __shared__ unsigned s_bin, s_rank;
    __shared__ float s_thr;
    int tid = threadIdx.x;
    if (g_fail) return;
    for (int i = tid; i < 2048; i += blockDim.x) sh[i] = g_hist2b[i];
    if (tid == 0) { s_bin = 0xffffffffu; s_rank = 0u; }
    __syncthreads();
    block_select2048(sh, g_rank2, &s_bin, &s_rank);
    __syncthreads();
    if (tid == 0) {
        if (s_bin == 0xffffffffu) {
            if (blockIdx.x == 0) g_fail = 1u;
            s_thr = __int_as_float(0x7f800000);   // +inf -> no fixup writes
        } else {
            float thr = key2f(g_b2base + s_bin);
            s_thr = thr;
            if (blockIdx.x == 0) g_threshold = thr;
        }
    }
    __syncthreads();
    const float thr = s_thr;
    const unsigned nc = g_count;
    const unsigned stride = gridDim.x * blockDim.x;
    for (unsigned i = blockIdx.x * blockDim.x + threadIdx.x; i < nc; i += stride) {
        if (key2f(g_cand[i]) >= thr) out[g_cidx[i]] = 1.0f;
    }
}

// ---------------- fallback: exact 2-pass 16-bit radix, one block ------------
// Never taken on sane inputs (launch cost only); correct for any input.
__global__ void f_all(const float* __restrict__ x, int n, unsigned idx) {
    if (!g_fail) return;
    __shared__ unsigned s_part[1024];
    __shared__ int s_seg;
    __shared__ unsigned s_segexcl, s_fb, s_fr;
    int tid = threadIdx.x;
    for (int b = tid; b < 65536; b += 1024) g_hist64k[b] = 0u;
    __syncthreads();
    for (int i = tid; i < n; i += blockDim.x)
        atomicAdd(&g_hist64k[f2key(x[i]) >> 16], 1u);
    __syncthreads();
    for (int phase = 0; phase < 2; phase++) {
        unsigned target = (phase == 0) ? idx : s_fr;
        if (tid == 0) s_seg = -1;
        unsigned my = 0u;
        for (int b = tid * 64; b < tid * 64 + 64; b++) my += g_hist64k[b];
        s_part[tid] = my;
        __syncthreads();
        for (int off = 1; off < 1024; off <<= 1) {
            unsigned t = (tid >= off) ? s_part[tid - off] : 0u;
            __syncthreads();
            s_part[tid] += t;
            __syncthreads();
        }
        unsigned incl = s_part[tid], excl = incl - my;
        if (my && target >= excl && target < incl) { s_seg = tid; s_segexcl = excl; }
        __syncthreads();
        if (tid == 0 && s_seg >= 0) {
            unsigned cum = s_segexcl;
            for (int b = s_seg * 64; b < s_seg * 64 + 64; b++) {
                unsigned c = g_hist64k[b];
                if (target >= cum && target < cum + c) {
                    if (phase == 0) { s_fb = (unsigned)b; s_fr = target - cum; }
                    else g_threshold = key2f((s_fb << 16) | (unsigned)b);
                    break;
                }
                cum += c;
            }
        }
        __syncthreads();
        for (int b = tid; b < 65536; b += 1024) g_hist64k[b] = 0u;
        __syncthreads();
        if (phase == 0) {
            unsigned fb = s_fb;
            for (int i = tid; i < n; i += blockDim.x) {
                unsigned key = f2key(x[i]);
                if ((key >> 16) == fb) atomicAdd(&g_hist64k[key & 0xffffu], 1u);
            }
            __syncthreads();
        }
    }
}

__global__ void f_mask(const float* __restrict__ x, float* __restrict__ out, int n) {
    if (!g_fail) return;
    const float thr = g_threshold;
    const int stride = gridDim.x * blockDim.x;
    for (int i = blockIdx.x * blockDim.x + threadIdx.x; i < n; i += stride)
        out[i] = (x[i] >= thr) ? 1.0f : 0.0f;
}

__global__ void k_fill0(float* __restrict__ out, int n) {
    const int stride = gridDim.x * blockDim.x;
    for (int i = blockIdx.x * blockDim.x + threadIdx.x; i < n; i += stride)
        out[i] = 0.0f;
}

extern "C" void kernel_launch(void* const* d_in, const int* in_sizes, int n_in,
                              void* d_out, int out_size) {
    const float* x = (const float*)d_in[0];
    float* out = (float*)d_out;
    const long long n = (long long)in_sizes[0];
    const long long k = (long long)((double)n * 0.9);
    if (k <= 0) { k_fill0<<<1184, 256>>>(out, (int)n); return; }
    const unsigned idx = (unsigned)(n - k);   // 0-indexed ascending rank
    const int n4 = (int)(n >> 2);
    // sample count: 32 float4s per 1024-float4 chunk
    const long long full = n4 / 1024, rem = n4 % 1024;
    const long long m4 = full * 32 + (rem < 32 ? rem : 32);
    const long long m = m4 * 4;
    unsigned t_target = (unsigned)((double)idx * (double)m / (double)n);
    if (t_target >= (unsigned)m) t_target = (unsigned)m - 1u;
    const long long sample_threads = ((n4 + 1023) / 1024) * 32;

    k_sample<<<(unsigned)((sample_threads + 255) / 256), 256>>>((const float4*)x, n4);
    k_pick<<<1, 1024>>>(t_target);
    k_main<<<1184, 256>>>((const float4*)x, n4, out);
    if (n & 3) k_main_tail<<<1, 64>>>(x, (int)n, out);
    k_sel2<<<296, 256>>>(idx);
    k_fixup<<<296, 256>>>(out);
    // fallback (no-ops unless g_fail)
    f_all<<<1, 1024>>>(x, (int)n, idx);
    f_mask<<<1184, 256>>>(x, out, (int)n);
}

// round 9
// speedup vs baseline: 3.2607x; 1.8405x over previous
#include <cuda_runtime.h>

// Single persistent kernel: sampled radix-select threshold + fused mask.
// Grid-wide sense barrier (co-residency guaranteed via occupancy API).
// Key map (order-preserving): neg -> ~bits, pos -> bits|0x80000000.

#define BLOCK     256
#define MAXG      2048
#define REP       8
#define STAGE_CAP 2048
#define CAND_CAP  (1u << 22)
#define MARGIN    3000u
#define MAX_EXP   15

static __device__ unsigned g_shist[REP * 65536];  // replicated sample hist
static __device__ unsigned g_part[MAXG];          // per-block slice partials
static __device__ unsigned g_hist2048[2048];      // level-1 candidate hist
static __device__ unsigned g_hist2b[2048];        // level-2 candidate hist
static __device__ unsigned g_hist64k[65536];      // fallback-only hist
static __device__ unsigned g_below, g_count, g_overflow, g_fail;
static __device__ float    g_threshold;
static __device__ unsigned g_bar_count, g_bar_gen;
static __device__ unsigned g_cand[CAND_CAP];
static __device__ unsigned g_cidx[CAND_CAP];

__device__ __forceinline__ unsigned f2key(float f) {
    unsigned u = __float_as_uint(f);
    return (u & 0x80000000u) ? ~u : (u | 0x80000000u);
}
__device__ __forceinline__ float key2f(unsigned key) {
    unsigned u = (key & 0x80000000u) ? (key & 0x7fffffffu) : ~key;
    return __uint_as_float(u);
}

// Grid barrier: sync-then-elect arrive; release via gen bump; volatile spin.
__device__ __forceinline__ void gsync(int G) {
    __syncthreads();
    if (threadIdx.x == 0) {
        __threadfence();
        unsigned gen = *(volatile unsigned*)&g_bar_gen;
        if (atomicAdd(&g_bar_count, 1u) == (unsigned)G - 1u) {
            g_bar_count = 0u;
            __threadfence();
            atomicAdd(&g_bar_gen, 1u);
        } else {
            while (*(volatile unsigned*)&g_bar_gen == gen) __nanosleep(64);
        }
        __threadfence();
    }
    __syncthreads();
}

// Block-parallel rank-select over smem hist (nb <= 2048, blockDim 256).
// Caller inits *o_bin = ~0u (+sync) before; ends with syncthreads.
__device__ __forceinline__ void bsel(const unsigned* h, int nb, unsigned target,
                                     unsigned* o_bin, unsigned* o_rank,
                                     unsigned* s_wofs) {
    int tid = threadIdx.x, lane = tid & 31, wid = tid >> 5;
    int C = (nb + BLOCK - 1) / BLOCK;
    int base = tid * C;
    unsigned my = 0u;
    for (int j = 0; j < C; j++) { int b = base + j; if (b < nb) my += h[b]; }
    unsigned v = my;
#pragma unroll
    for (int off = 1; off < 32; off <<= 1) {
        unsigned t = __shfl_up_sync(0xffffffffu, v, off);
        if (lane >= off) v += t;
    }
    if (lane == 31) s_wofs[wid + 1] = v;
    if (tid == 0) s_wofs[0] = 0u;
    __syncthreads();
    if (tid == 0) for (int w = 1; w <= 8; w++) s_wofs[w] += s_wofs[w - 1];
    __syncthreads();
    unsigned excl = s_wofs[wid] + v - my;
    if (my && target >= excl && target < excl + my) {
        unsigned cum = excl;
        for (int j = 0; j < C; j++) {
            int b = base + j; if (b >= nb) break;
            unsigned c = h[b];
            if (target < cum + c) { *o_bin = (unsigned)b; *o_rank = target - cum; break; }
            cum += c;
        }
    }
    __syncthreads();
}

__global__ __launch_bounds__(BLOCK, 6)
void k_fused(const float4* __restrict__ x4, int n4,
             const float* __restrict__ x, int n,
             float* __restrict__ out, unsigned idx, unsigned t_target, int G) {
    __shared__ unsigned s_a[2048];       // pick: slice | main: cand keys | D: lvl2 hist
    __shared__ unsigned s_b[2048];       // pick: window | main: cand idx
    __shared__ unsigned s_h[2048];       // staging: partials/hists | main: lvl1 hist
    __shared__ unsigned s_wofs[9];
    __shared__ unsigned s_obin, s_orank, s_cnt, s_below, s_base;
    __shared__ unsigned s_klo, s_shift, s_pickok;
    __shared__ float    s_flo, s_fhi;
    const int tid = threadIdx.x;
    const int bid = blockIdx.x;
    const int gstride = G * BLOCK;

    if (bid == 0 && tid == 0) g_fail = 0u;   // prev replay's fallback is done

    // ---- Phase A: sample every 32nd float4 into replicated 64K hist ----
    const int S4 = (n4 + 31) / 32;
    {
        const unsigned rbase = (unsigned)(bid & (REP - 1)) * 65536u;
        for (int j = bid * BLOCK + tid; j < S4; j += gstride) {
            float4 v = __ldg(&x4[j * 32]);
            atomicAdd(&g_shist[rbase + (f2key(v.x) >> 16)], 1u);
            atomicAdd(&g_shist[rbase + (f2key(v.y) >> 16)], 1u);
            atomicAdd(&g_shist[rbase + (f2key(v.z) >> 16)], 1u);
            atomicAdd(&g_shist[rbase + (f2key(v.w) >> 16)], 1u);
        }
    }
    gsync(G);

    // ---- Phase B: per-block slice partial sums ----
    const int SLICE = (65536 + G - 1) / G;
    {
        int base = bid * SLICE;
        unsigned sum = 0u;
        for (int i = tid; i < SLICE; i += BLOCK) {
            int b = base + i;
            if (b < 65536) {
                unsigned s = 0u;
#pragma unroll
                for (int r = 0; r < REP; r++) s += g_shist[r * 65536 + b];
                sum += s;
            }
        }
#pragma unroll
        for (int off = 16; off > 0; off >>= 1)
            sum += __shfl_down_sync(0xffffffffu, sum, off);
        if ((tid & 31) == 0) s_wofs[tid >> 5] = sum;
        __syncthreads();
        if (tid == 0) {
            unsigned t = 0u;
            for (int w = 0; w < 8; w++) t += s_wofs[w];
            g_part[bid] = t;
        }
        __syncthreads();
    }
    gsync(G);

    // ---- Phase C1: every block computes the SAME pick locally ----
    {
        for (int i = tid; i < G; i += BLOCK) s_h[i] = g_part[i];
        if (tid == 0) { s_obin = 0xffffffffu; s_pickok = 0u; }
        __syncthreads();
        bsel(s_h, G, t_target, &s_obin, &s_orank, s_wofs);
        int seg = (int)s_obin;
        unsigned segrank = s_orank;
        if (seg != -1) {
            int base = seg * SLICE;
            int nb = 65536 - base; if (nb > SLICE) nb = SLICE;
            for (int i = tid; i < nb; i += BLOCK) {
                unsigned s = 0u;
#pragma unroll
                for (int r = 0; r < REP; r++) s += g_shist[r * 65536 + base + i];
                s_a[i] = s;
            }
            if (tid == 0) s_obin = 0xffffffffu;
            __syncthreads();
            bsel(s_a, nb, segrank, &s_obin, &s_orank, s_wofs);
            int bc = (s_obin == 0xffffffffu) ? -1 : base + (int)s_obin;
            if (bc >= 0) {
                int w0 = bc - 16;
                for (int i = tid; i < 33; i += BLOCK) {
                    int b = w0 + i;
                    unsigned s = 0u;
                    if (b >= 0 && b < 65536) {
#pragma unroll
                        for (int r = 0; r < REP; r++) s += g_shist[r * 65536 + b];
                    }
                    s_b[i] = s;
                }
                __syncthreads();
                if (tid == 0) {
                    int lo = 16; unsigned accL = 0u;
                    while ((w0 + lo) > 0 && accL < MARGIN && (16 - lo) < MAX_EXP) { lo--; accL += s_b[lo]; }
                    int hi = 16; unsigned accR = 0u;
                    while ((w0 + hi) < 65535 && accR < MARGIN && (hi - 16) < MAX_EXP) { hi++; accR += s_b[hi]; }
                    int lob = w0 + lo, hib = w0 + hi;
                    if (lob == 0x8000) lob--;
                    if (hib == 0x7fff) hib++;
                    if (lob < 0) lob = 0;
                    if (hib > 65535) hib = 65535;
                    unsigned klo = (unsigned)lob << 16;
                    unsigned khi = ((unsigned)hib << 16) | 0xffffu;
                    unsigned range = khi - klo, sh = 0u;
                    while ((range >> sh) >= 2048u) sh++;
                    s_klo = klo; s_shift = sh;
                    s_flo = key2f(klo); s_fhi = key2f(khi);
                    s_pickok = 1u;
                }
            }
        }
        __syncthreads();
        if (!s_pickok && tid == 0) { s_flo = 1.0f; s_fhi = 0.0f; s_klo = 0u; s_shift = 0u; }
        __syncthreads();
    }

    // ---- Phase C2: main fused pass ----
    const float flo = s_flo, fhi = s_fhi;
    const unsigned klo = s_klo, sh = s_shift;
    const unsigned pickok = s_pickok;
    __syncthreads();   // C1's s_b window walk done before s_b reuse below
    {
        for (int i = tid; i < 2048; i += BLOCK) s_h[i] = 0u;
        if (tid == 0) { s_cnt = 0u; s_below = 0u; }
        __syncthreads();
        unsigned below = 0u;
        float4* o4 = (float4*)out;
#pragma unroll 4
        for (int i = bid * BLOCK + tid; i < n4; i += gstride) {
            float4 v = __ldcs(&x4[i]);
            float4 rr;
            rr.x = (v.x > fhi) ? 1.0f : 0.0f;
            rr.y = (v.y > fhi) ? 1.0f : 0.0f;
            rr.z = (v.z > fhi) ? 1.0f : 0.0f;
            rr.w = (v.w > fhi) ? 1.0f : 0.0f;
            __stcs(&o4[i], rr);
            below += (v.x < flo) + (v.y < flo) + (v.z < flo) + (v.w < flo);
            unsigned e = (unsigned)i * 4u;
            if (v.x >= flo && v.x <= fhi) {
                unsigned key = f2key(v.x);
                unsigned p = atomicAdd(&s_cnt, 1u);
                if (p < STAGE_CAP) { s_a[p] = key; s_b[p] = e; atomicAdd(&s_h[min((key - klo) >> sh, 2047u)], 1u); }
            }
            if (v.y >= flo && v.y <= fhi) {
                unsigned key = f2key(v.y);
                unsigned p = atomicAdd(&s_cnt, 1u);
                if (p < STAGE_CAP) { s_a[p] = key; s_b[p] = e + 1u; atomicAdd(&s_h[min((key - klo) >> sh, 2047u)], 1u); }
            }
            if (v.z >= flo && v.z <= fhi) {
                unsigned key = f2key(v.z);
                unsigned p = atomicAdd(&s_cnt, 1u);
                if (p < STAGE_CAP) { s_a[p] = key; s_b[p] = e + 2u; atomicAdd(&s_h[min((key - klo) >> sh, 2047u)], 1u); }
            }
            if (v.w >= flo && v.w <= fhi) {
                unsigned key = f2key(v.w);
                unsigned p = atomicAdd(&s_cnt, 1u);
                if (p < STAGE_CAP) { s_a[p] = key; s_b[p] = e + 3u; atomicAdd(&s_h[min((key - klo) >> sh, 2047u)], 1u); }
            }
        }
#pragma unroll
        for (int off = 16; off > 0; off >>= 1)
            below += __shfl_down_sync(0xffffffffu, below, off);
        if ((tid & 31) == 0) atomicAdd(&s_below, below);
        __syncthreads();
        unsigned cnt = s_cnt < STAGE_CAP ? s_cnt : STAGE_CAP;
        if (tid == 0) {
            if (s_cnt > STAGE_CAP) atomicExch(&g_overflow, 1u);
            atomicAdd(&g_below, s_below);
            s_base = atomicAdd(&g_count, cnt);
        }
        __syncthreads();
        unsigned base = s_base;
        for (unsigned i = tid; i < cnt; i += BLOCK) {
            g_cand[base + i] = s_a[i];
            g_cidx[base + i] = s_b[i];
        }
        for (int i = tid; i < 2048; i += BLOCK)
            if (s_h[i]) atomicAdd(&g_hist2048[i], s_h[i]);
        // scalar tail (n % 4), block 0 only
        if (bid == 0) {
            for (int i = (n & ~3) + tid; i < n; i += BLOCK) {
                float v = x[i];
                out[i] = (v > fhi) ? 1.0f : 0.0f;
                if (v < flo) atomicAdd(&g_below, 1u);
                else if (v >= flo && v <= fhi) {
                    unsigned key = f2key(v);
                    unsigned p = atomicAdd(&g_count, 1u);
                    if (p < CAND_CAP) {
                        g_cand[p] = key; g_cidx[p] = (unsigned)i;
                        atomicAdd(&g_hist2048[min((key - klo) >> sh, 2047u)], 1u);
                    } else atomicExch(&g_overflow, 1u);
                }
            }
        }
    }
    gsync(G);

    // ---- Phase D: level-1 select (local) + level-2 candidate hist ----
    unsigned nc, ok, b2base = 0u, rank2 = 0u, w = 1u;
    {
        for (int i = tid; i < 2048; i += BLOCK) s_h[i] = g_hist2048[i];
        unsigned below_g = g_below;
        nc = g_count;
        unsigned ovf = g_overflow;
        ok = pickok && (!ovf) && (idx >= below_g) && ((idx - below_g) < nc) && (nc <= CAND_CAP);
        if (tid == 0) s_obin = 0xffffffffu;
        __syncthreads();
        if (ok) {
            bsel(s_h, 2048, idx - below_g, &s_obin, &s_orank, s_wofs);
            if (s_obin == 0xffffffffu) ok = 0u;
            else {
                b2base = klo + (s_obin << sh);
                rank2 = s_orank;
                w = 1u << sh;
                for (int i = tid; i < 2048; i += BLOCK) s_a[i] = 0u;
                __syncthreads();
                for (unsigned i = bid * BLOCK + tid; i < nc; i += (unsigned)gstride) {
                    unsigned off = g_cand[i] - b2base;
                    if (off < w) atomicAdd(&s_a[min(off, 2047u)], 1u);
                }
                __syncthreads();
                unsigned wcap = w < 2048u ? w : 2048u;
                for (unsigned i = tid; i < wcap; i += BLOCK)
                    if (s_a[i]) atomicAdd(&g_hist2b[i], s_a[i]);
            }
        }
        // zero sample hist slice + partials (last read in phase C1)
        int base = bid * SLICE;
        for (int i = tid; i < SLICE; i += BLOCK) {
            int b = base + i;
            if (b < 65536) {
#pragma unroll
                for (int r = 0; r < REP; r++) g_shist[r * 65536 + b] = 0u;
            }
        }
        if (tid == 0) g_part[bid] = 0u;
    }
    gsync(G);

    // ---- Phase E: threshold select (local) + cleanup + fixup ----
    {
        for (int i = tid; i < 2048; i += BLOCK) s_h[i] = g_hist2b[i];
        if (tid == 0) s_obin = 0xffffffffu;
        __syncthreads();
        float thr = __int_as_float(0x7f800000);
        if (ok) {
            int nb = (int)(w < 2048u ? w : 2048u);
            bsel(s_h, nb, rank2, &s_obin, &s_orank, s_wofs);
            if (s_obin == 0xffffffffu) ok = 0u;
            else thr = key2f(b2base + s_obin);
        }
        gsync(G);
        // cleanup (everyone staged what they need)
        for (int i = bid * BLOCK + tid; i < 2048; i += gstride) {
            g_hist2048[i] = 0u;
            g_hist2b[i] = 0u;
        }
        if (bid == 0 && tid == 0) {
            g_below = 0u; g_count = 0u; g_overflow = 0u;
            if (!ok) g_fail = 1u;
            else g_threshold = thr;
        }
        if (ok) {
            for (unsigned i = bid * BLOCK + tid; i < nc; i += (unsigned)gstride)
                if (key2f(g_cand[i]) >= thr) out[g_cidx[i]] = 1.0f;
        }
    }
}

// ---------------- fallback: exact 2-pass 16-bit radix, one block ------------
__global__ void f_all(const float* __restrict__ x, int n, unsigned idx) {
    if (!g_fail) return;
    __shared__ unsigned s_part[1024];
    __shared__ int s_seg;
    __shared__ unsigned s_segexcl, s_fb, s_fr;
    int tid = threadIdx.x;
    for (int b = tid; b < 65536; b += 1024) g_hist64k[b] = 0u;
    __syncthreads();
    for (int i = tid; i < n; i += blockDim.x)
        atomicAdd(&g_hist64k[f2key(x[i]) >> 16], 1u);
    __syncthreads();
    for (int phase = 0; phase < 2; phase++) {
        unsigned target = (phase == 0) ? idx : s_fr;
        if (tid == 0) s_seg = -1;
        unsigned my = 0u;
        for (int b = tid * 64; b < tid * 64 + 64; b++) my += g_hist64k[b];
        s_part[tid] = my;
        __syncthreads();
        for (int off = 1; off < 1024; off <<= 1) {
            unsigned t = (tid >= off) ? s_part[tid - off] : 0u;
            __syncthreads();
            s_part[tid] += t;
            __syncthreads();
        }
        unsigned incl = s_part[tid], excl = incl - my;
        if (my && target >= excl && target < incl) { s_seg = tid; s_segexcl = excl; }
        __syncthreads();
        if (tid == 0 && s_seg >= 0) {
            unsigned cum = s_segexcl;
            for (int b = s_seg * 64; b < s_seg * 64 + 64; b++) {
                unsigned c = g_hist64k[b];
                if (target >= cum && target < cum + c) {
                    if (phase == 0) { s_fb = (unsigned)b; s_fr = target - cum; }
                    else g_threshold = key2f((s_fb << 16) | (unsigned)b);
                    break;
                }
                cum += c;
            }
        }
        __syncthreads();
        for (int b = tid; b < 65536; b += 1024) g_hist64k[b] = 0u;
        __syncthreads();
        if (phase == 0) {
            unsigned fb = s_fb;
            for (int i = tid; i < n; i += blockDim.x) {
                unsigned key = f2key(x[i]);
                if ((key >> 16) == fb) atomicAdd(&g_hist64k[key & 0xffffu], 1u);
            }
            __syncthreads();
        }
    }
}

__global__ void f_mask(const float* __restrict__ x, float* __restrict__ out, int n) {
    if (!g_fail) return;
    const float thr = g_threshold;
    const int stride = gridDim.x * blockDim.x;
    for (int i = blockIdx.x * blockDim.x + threadIdx.x; i < n; i += stride)
        out[i] = (x[i] >= thr) ? 1.0f : 0.0f;
}

__global__ void k_fill0(float* __restrict__ out, int n) {
    const int stride = gridDim.x * blockDim.x;
    for (int i = blockIdx.x * blockDim.x + threadIdx.x; i < n; i += stride)
        out[i] = 0.0f;
}

extern "C" void kernel_launch(void* const* d_in, const int* in_sizes, int n_in,
                              void* d_out, int out_size) {
    const float* x = (const float*)d_in[0];
    float* out = (float*)d_out;
    const long long n = (long long)in_sizes[0];
    const long long k = (long long)((double)n * 0.9);
    if (k <= 0) { k_fill0<<<1184, 256>>>(out, (int)n); return; }
    const unsigned idx = (unsigned)(n - k);   // 0-indexed ascending rank
    const int n4 = (int)(n >> 2);
    const int S4 = (n4 + 31) / 32;
    const long long m = (long long)S4 * 4;
    unsigned t_target = 0u;
    if (m > 0) {
        t_target = (unsigned)((double)idx * (double)m / (double)n);
        if (t_target >= (unsigned)m) t_target = (unsigned)m - 1u;
    }

    int sm = 148, occ = 6, dev = 0;
    cudaGetDevice(&dev);
    cudaDeviceGetAttribute(&sm, cudaDevAttrMultiProcessorCount, dev);
    cudaOccupancyMaxActiveBlocksPerMultiprocessor(&occ, k_fused, BLOCK, 0);
    if (occ > 6) occ = 6;
    if (occ < 1) occ = 1;
    int G = sm * occ;
    if (G > MAXG) G = MAXG;
    if (G < 1) G = 1;

    k_fused<<<G, BLOCK>>>((const float4*)x, n4, x, (int)n, out, idx, t_target, G);
    // fallback (no-ops unless g_fail)
    f_all<<<1, 1024>>>(x, (int)n, idx);
    f_mask<<<1184, 256>>>(x, out, (int)n);
}

// round 10
// speedup vs baseline: 3.3968x; 1.0417x over previous
#include <cuda_runtime.h>

// Single persistent kernel: sampled radix-select threshold + fused mask.
// Grid-wide sense barrier (co-residency guaranteed via occupancy API).
// Key map (order-preserving): neg -> ~bits, pos -> bits|0x80000000.

#define BLOCK     256
#define MAXG      2048
#define REP       8
#define STAGE_CAP 2048
#define CAND_CAP  (1u << 22)
#define MARGIN    3000u
#define MAX_EXP   15

static __device__ unsigned g_shist[REP * 65536];  // replicated sample hist
static __device__ unsigned g_part[MAXG];          // per-block slice partials
static __device__ unsigned g_hist2048[2048];      // level-1 candidate hist
static __device__ unsigned g_hist2b[2048];        // level-2 candidate hist
static __device__ unsigned g_hist64k[65536];      // fallback-only hist
static __device__ unsigned g_below, g_count, g_overflow, g_fail;
static __device__ float    g_threshold;
static __device__ unsigned g_bar_count, g_bar_gen;
static __device__ unsigned g_cand[CAND_CAP];
static __device__ unsigned g_cidx[CAND_CAP];

__device__ __forceinline__ unsigned f2key(float f) {
    unsigned u = __float_as_uint(f);
    return (u & 0x80000000u) ? ~u : (u | 0x80000000u);
}
__device__ __forceinline__ float key2f(unsigned key) {
    unsigned u = (key & 0x80000000u) ? (key & 0x7fffffffu) : ~key;
    return __uint_as_float(u);
}

// Grid barrier: sync-then-elect arrive; release via gen bump; volatile spin.
__device__ __forceinline__ void gsync(int G) {
    __syncthreads();
    if (threadIdx.x == 0) {
        __threadfence();
        unsigned gen = *(volatile unsigned*)&g_bar_gen;
        if (atomicAdd(&g_bar_count, 1u) == (unsigned)G - 1u) {
            g_bar_count = 0u;
            __threadfence();
            atomicAdd(&g_bar_gen, 1u);
        } else {
            while (*(volatile unsigned*)&g_bar_gen == gen) __nanosleep(64);
        }
        __threadfence();
    }
    __syncthreads();
}

// Block-parallel rank-select over smem hist (nb <= 2048, blockDim 256).
// Caller inits *o_bin = ~0u (+sync) before; ends with syncthreads.
__device__ __forceinline__ void bsel(const unsigned* h, int nb, unsigned target,
                                     unsigned* o_bin, unsigned* o_rank,
                                     unsigned* s_wofs) {
    int tid = threadIdx.x, lane = tid & 31, wid = tid >> 5;
    int C = (nb + BLOCK - 1) / BLOCK;
    int base = tid * C;
    unsigned my = 0u;
    for (int j = 0; j < C; j++) { int b = base + j; if (b < nb) my += h[b]; }
    unsigned v = my;
#pragma unroll
    for (int off = 1; off < 32; off <<= 1) {
        unsigned t = __shfl_up_sync(0xffffffffu, v, off);
        if (lane >= off) v += t;
    }
    if (lane == 31) s_wofs[wid + 1] = v;
    if (tid == 0) s_wofs[0] = 0u;
    __syncthreads();
    if (tid == 0) for (int w = 1; w <= 8; w++) s_wofs[w] += s_wofs[w - 1];
    __syncthreads();
    unsigned excl = s_wofs[wid] + v - my;
    if (my && target >= excl && target < excl + my) {
        unsigned cum = excl;
        for (int j = 0; j < C; j++) {
            int b = base + j; if (b >= nb) break;
            unsigned c = h[b];
            if (target < cum + c) { *o_bin = (unsigned)b; *o_rank = target - cum; break; }
            cum += c;
        }
    }
    __syncthreads();
}

__global__ __launch_bounds__(BLOCK, 6)
void k_fused(const float4* __restrict__ x4, int n4,
             const float* __restrict__ x, int n,
             float* __restrict__ out, unsigned idx, unsigned t_target, int G) {
    __shared__ unsigned s_a[2048];       // pick: slice | main: cand keys | D: lvl2 hist
    __shared__ unsigned s_b[2048];       // pick: window | main: cand idx
    __shared__ unsigned s_h[2048];       // staging: partials/hists | main: lvl1 hist
    __shared__ unsigned s_wofs[9];
    __shared__ unsigned s_obin, s_orank, s_cnt, s_below, s_base;
    __shared__ unsigned s_klo, s_shift, s_pickok;
    __shared__ float    s_flo, s_fhi;
    const int tid = threadIdx.x;
    const int bid = blockIdx.x;
    const int gstride = G * BLOCK;

    if (bid == 0 && tid == 0) g_fail = 0u;   // prev replay's fallback is done

    // ---- Phase A: sample every 32nd float4 into replicated 64K hist ----
    const int S4 = (n4 + 31) / 32;
    {
        const unsigned rbase = (unsigned)(bid & (REP - 1)) * 65536u;
        for (int j = bid * BLOCK + tid; j < S4; j += gstride) {
            float4 v = __ldg(&x4[j * 32]);
            atomicAdd(&g_shist[rbase + (f2key(v.x) >> 16)], 1u);
            atomicAdd(&g_shist[rbase + (f2key(v.y) >> 16)], 1u);
            atomicAdd(&g_shist[rbase + (f2key(v.z) >> 16)], 1u);
            atomicAdd(&g_shist[rbase + (f2key(v.w) >> 16)], 1u);
        }
    }
    gsync(G);

    // ---- Phase B: per-block slice partial sums ----
    const int SLICE = (65536 + G - 1) / G;
    {
        int base = bid * SLICE;
        unsigned sum = 0u;
        for (int i = tid; i < SLICE; i += BLOCK) {
            int b = base + i;
            if (b < 65536) {
                unsigned s = 0u;
#pragma unroll
                for (int r = 0; r < REP; r++) s += g_shist[r * 65536 + b];
                sum += s;
            }
        }
#pragma unroll
        for (int off = 16; off > 0; off >>= 1)
            sum += __shfl_down_sync(0xffffffffu, sum, off);
        if ((tid & 31) == 0) s_wofs[tid >> 5] = sum;
        __syncthreads();
        if (tid == 0) {
            unsigned t = 0u;
            for (int w = 0; w < 8; w++) t += s_wofs[w];
            g_part[bid] = t;
        }
        __syncthreads();
    }
    gsync(G);

    // ---- Phase C1: every block computes the SAME pick locally ----
    {
        for (int i = tid; i < G; i += BLOCK) s_h[i] = g_part[i];
        if (tid == 0) { s_obin = 0xffffffffu; s_pickok = 0u; }
        __syncthreads();
        bsel(s_h, G, t_target, &s_obin, &s_orank, s_wofs);
        int seg = (int)s_obin;
        unsigned segrank = s_orank;
        if (seg != -1) {
            int base = seg * SLICE;
            int nb = 65536 - base; if (nb > SLICE) nb = SLICE;
            for (int i = tid; i < nb; i += BLOCK) {
                unsigned s = 0u;
#pragma unroll
                for (int r = 0; r < REP; r++) s += g_shist[r * 65536 + base + i];
                s_a[i] = s;
            }
            if (tid == 0) s_obin = 0xffffffffu;
            __syncthreads();
            bsel(s_a, nb, segrank, &s_obin, &s_orank, s_wofs);
            int bc = (s_obin == 0xffffffffu) ? -1 : base + (int)s_obin;
            if (bc >= 0) {
                int w0 = bc - 16;
                for (int i = tid; i < 33; i += BLOCK) {
                    int b = w0 + i;
                    unsigned s = 0u;
                    if (b >= 0 && b < 65536) {
#pragma unroll
                        for (int r = 0; r < REP; r++) s += g_shist[r * 65536 + b];
                    }
                    s_b[i] = s;
                }
                __syncthreads();
                if (tid == 0) {
                    int lo = 16; unsigned accL = 0u;
                    while ((w0 + lo) > 0 && accL < MARGIN && (16 - lo) < MAX_EXP) { lo--; accL += s_b[lo]; }
                    int hi = 16; unsigned accR = 0u;
                    while ((w0 + hi) < 65535 && accR < MARGIN && (hi - 16) < MAX_EXP) { hi++; accR += s_b[hi]; }
                    int lob = w0 + lo, hib = w0 + hi;
                    if (lob == 0x8000) lob--;
                    if (hib == 0x7fff) hib++;
                    if (lob < 0) lob = 0;
                    if (hib > 65535) hib = 65535;
                    unsigned klo = (unsigned)lob << 16;
                    unsigned khi = ((unsigned)hib << 16) | 0xffffu;
                    unsigned range = khi - klo, sh = 0u;
                    while ((range >> sh) >= 2048u) sh++;
                    s_klo = klo; s_shift = sh;
                    s_flo = key2f(klo); s_fhi = key2f(khi);
                    s_pickok = 1u;
                }
            }
        }
        __syncthreads();
        if (!s_pickok && tid == 0) { s_flo = 1.0f; s_fhi = 0.0f; s_klo = 0u; s_shift = 0u; }
        __syncthreads();
    }

    // ---- Phase C2: main fused pass (4x batched loads for MLP) ----
    const float flo = s_flo, fhi = s_fhi;
    const unsigned klo = s_klo, sh = s_shift;
    const unsigned pickok = s_pickok;
    __syncthreads();   // C1's s_b window walk done before s_b reuse below
    {
        for (int i = tid; i < 2048; i += BLOCK) s_h[i] = 0u;
        if (tid == 0) { s_cnt = 0u; s_below = 0u; }
        __syncthreads();
        unsigned below = 0u;
        float4* o4 = (float4*)out;
        int i = bid * BLOCK + tid;
        // batched: 4 independent coalesced loads in flight per iteration
        for (; i + 3 * gstride < n4; i += 4 * gstride) {
            float4 v0 = __ldcs(&x4[i]);
            float4 v1 = __ldcs(&x4[i + gstride]);
            float4 v2 = __ldcs(&x4[i + 2 * gstride]);
            float4 v3 = __ldcs(&x4[i + 3 * gstride]);
            float4 r0, r1, r2, r3;
            r0.x = (v0.x > fhi) ? 1.0f : 0.0f; r0.y = (v0.y > fhi) ? 1.0f : 0.0f;
            r0.z = (v0.z > fhi) ? 1.0f : 0.0f; r0.w = (v0.w > fhi) ? 1.0f : 0.0f;
            r1.x = (v1.x > fhi) ? 1.0f : 0.0f; r1.y = (v1.y > fhi) ? 1.0f : 0.0f;
            r1.z = (v1.z > fhi) ? 1.0f : 0.0f; r1.w = (v1.w > fhi) ? 1.0f : 0.0f;
            r2.x = (v2.x > fhi) ? 1.0f : 0.0f; r2.y = (v2.y > fhi) ? 1.0f : 0.0f;
            r2.z = (v2.z > fhi) ? 1.0f : 0.0f; r2.w = (v2.w > fhi) ? 1.0f : 0.0f;
            r3.x = (v3.x > fhi) ? 1.0f : 0.0f; r3.y = (v3.y > fhi) ? 1.0f : 0.0f;
            r3.z = (v3.z > fhi) ? 1.0f : 0.0f; r3.w = (v3.w > fhi) ? 1.0f : 0.0f;
            __stcs(&o4[i], r0);
            __stcs(&o4[i + gstride], r1);
            __stcs(&o4[i + 2 * gstride], r2);
            __stcs(&o4[i + 3 * gstride], r3);
            below += (v0.x < flo) + (v0.y < flo) + (v0.z < flo) + (v0.w < flo);
            below += (v1.x < flo) + (v1.y < flo) + (v1.z < flo) + (v1.w < flo);
            below += (v2.x < flo) + (v2.y < flo) + (v2.z < flo) + (v2.w < flo);
            below += (v3.x < flo) + (v3.y < flo) + (v3.z < flo) + (v3.w < flo);
            bool c0 = (v0.x >= flo && v0.x <= fhi) || (v0.y >= flo && v0.y <= fhi) ||
                      (v0.z >= flo && v0.z <= fhi) || (v0.w >= flo && v0.w <= fhi);
            bool c1 = (v1.x >= flo && v1.x <= fhi) || (v1.y >= flo && v1.y <= fhi) ||
                      (v1.z >= flo && v1.z <= fhi) || (v1.w >= flo && v1.w <= fhi);
            bool c2 = (v2.x >= flo && v2.x <= fhi) || (v2.y >= flo && v2.y <= fhi) ||
                      (v2.z >= flo && v2.z <= fhi) || (v2.w >= flo && v2.w <= fhi);
            bool c3 = (v3.x >= flo && v3.x <= fhi) || (v3.y >= flo && v3.y <= fhi) ||
                      (v3.z >= flo && v3.z <= fhi) || (v3.w >= flo && v3.w <= fhi);
            unsigned am = __activemask();
            if (__ballot_sync(am, c0 || c1 || c2 || c3)) {
#pragma unroll
                for (int u = 0; u < 4; u++) {
                    float4 v = (u == 0) ? v0 : (u == 1) ? v1 : (u == 2) ? v2 : v3;
                    unsigned e = (unsigned)(i + u * gstride) * 4u;
                    if (v.x >= flo && v.x <= fhi) {
                        unsigned key = f2key(v.x);
                        unsigned p = atomicAdd(&s_cnt, 1u);
                        if (p < STAGE_CAP) { s_a[p] = key; s_b[p] = e; atomicAdd(&s_h[min((key - klo) >> sh, 2047u)], 1u); }
                    }
                    if (v.y >= flo && v.y <= fhi) {
                        unsigned key = f2key(v.y);
                        unsigned p = atomicAdd(&s_cnt, 1u);
                        if (p < STAGE_CAP) { s_a[p] = key; s_b[p] = e + 1u; atomicAdd(&s_h[min((key - klo) >> sh, 2047u)], 1u); }
                    }
                    if (v.z >= flo && v.z <= fhi) {
                        unsigned key = f2key(v.z);
                        unsigned p = atomicAdd(&s_cnt, 1u);
                        if (p < STAGE_CAP) { s_a[p] = key; s_b[p] = e + 2u; atomicAdd(&s_h[min((key - klo) >> sh, 2047u)], 1u); }
                    }
                    if (v.w >= flo && v.w <= fhi) {
                        unsigned key = f2key(v.w);
                        unsigned p = atomicAdd(&s_cnt, 1u);
                        if (p < STAGE_CAP) { s_a[p] = key; s_b[p] = e + 3u; atomicAdd(&s_h[min((key - klo) >> sh, 2047u)], 1u); }
                    }
                }
            }
        }
        // remainder (up to 3 grid-stride steps)
        for (; i < n4; i += gstride) {
            float4 v = __ldcs(&x4[i]);
            float4 rr;
            rr.x = (v.x > fhi) ? 1.0f : 0.0f;
            rr.y = (v.y > fhi) ? 1.0f : 0.0f;
            rr.z = (v.z > fhi) ? 1.0f : 0.0f;
            rr.w = (v.w > fhi) ? 1.0f : 0.0f;
            __stcs(&o4[i], rr);
            below += (v.x < flo) + (v.y < flo) + (v.z < flo) + (v.w < flo);
            unsigned e = (unsigned)i * 4u;
            if (v.x >= flo && v.x <= fhi) {
                unsigned key = f2key(v.x);
                unsigned p = atomicAdd(&s_cnt, 1u);
                if (p < STAGE_CAP) { s_a[p] = key; s_b[p] = e; atomicAdd(&s_h[min((key - klo) >> sh, 2047u)], 1u); }
            }
            if (v.y >= flo && v.y <= fhi) {
                unsigned key = f2key(v.y);
                unsigned p = atomicAdd(&s_cnt, 1u);
                if (p < STAGE_CAP) { s_a[p] = key; s_b[p] = e + 1u; atomicAdd(&s_h[min((key - klo) >> sh, 2047u)], 1u); }
            }
            if (v.z >= flo && v.z <= fhi) {
                unsigned key = f2key(v.z);
                unsigned p = atomicAdd(&s_cnt, 1u);
                if (p < STAGE_CAP) { s_a[p] = key; s_b[p] = e + 2u; atomicAdd(&s_h[min((key - klo) >> sh, 2047u)], 1u); }
            }
            if (v.w >= flo && v.w <= fhi) {
                unsigned key = f2key(v.w);
                unsigned p = atomicAdd(&s_cnt, 1u);
                if (p < STAGE_CAP) { s_a[p] = key; s_b[p] = e + 3u; atomicAdd(&s_h[min((key - klo) >> sh, 2047u)], 1u); }
            }
        }
#pragma unroll
        for (int off = 16; off > 0; off >>= 1)
            below += __shfl_down_sync(0xffffffffu, below, off);
        if ((tid & 31) == 0) atomicAdd(&s_below, below);
        __syncthreads();
        unsigned cnt = s_cnt < STAGE_CAP ? s_cnt : STAGE_CAP;
        if (tid == 0) {
            if (s_cnt > STAGE_CAP) atomicExch(&g_overflow, 1u);
            atomicAdd(&g_below, s_below);
            s_base = atomicAdd(&g_count, cnt);
        }
        __syncthreads();
        unsigned base = s_base;
        for (unsigned j = tid; j < cnt; j += BLOCK) {
            g_cand[base + j] = s_a[j];
            g_cidx[base + j] = s_b[j];
        }
        for (int j = tid; j < 2048; j += BLOCK)
            if (s_h[j]) atomicAdd(&g_hist2048[j], s_h[j]);
        // scalar tail (n % 4), block 0 only
        if (bid == 0) {
            for (int j = (n & ~3) + tid; j < n; j += BLOCK) {
                float v = x[j];
                out[j] = (v > fhi) ? 1.0f : 0.0f;
                if (v < flo) atomicAdd(&g_below, 1u);
                else if (v >= flo && v <= fhi) {
                    unsigned key = f2key(v);
                    unsigned p = atomicAdd(&g_count, 1u);
                    if (p < CAND_CAP) {
                        g_cand[p] = key; g_cidx[p] = (unsigned)j;
                        atomicAdd(&g_hist2048[min((key - klo) >> sh, 2047u)], 1u);
                    } else atomicExch(&g_overflow, 1u);
                }
            }
        }
    }
    gsync(G);

    // ---- Phase D: level-1 select (local) + level-2 candidate hist ----
    unsigned nc, ok, b2base = 0u, rank2 = 0u, w = 1u;
    {
        for (int i = tid; i < 2048; i += BLOCK) s_h[i] = g_hist2048[i];
        unsigned below_g = g_below;
        nc = g_count;
        unsigned ovf = g_overflow;
        ok = pickok && (!ovf) && (idx >= below_g) && ((idx - below_g) < nc) && (nc <= CAND_CAP);
        if (tid == 0) s_obin = 0xffffffffu;
        __syncthreads();
        if (ok) {
            bsel(s_h, 2048, idx - below_g, &s_obin, &s_orank, s_wofs);
            if (s_obin == 0xffffffffu) ok = 0u;
            else {
                b2base = klo + (s_obin << sh);
                rank2 = s_orank;
                w = 1u << sh;
                for (int i = tid; i < 2048; i += BLOCK) s_a[i] = 0u;
                __syncthreads();
                for (unsigned i = bid * BLOCK + tid; i < nc; i += (unsigned)gstride) {
                    unsigned off = g_cand[i] - b2base;
                    if (off < w) atomicAdd(&s_a[min(off, 2047u)], 1u);
                }
                __syncthreads();
                unsigned wcap = w < 2048u ? w : 2048u;
                for (unsigned i = tid; i < wcap; i += BLOCK)
                    if (s_a[i]) atomicAdd(&g_hist2b[i], s_a[i]);
            }
        }
        // zero sample hist slice + partials (last read in phase C1)
        int base = bid * SLICE;
        for (int i = tid; i < SLICE; i += BLOCK) {
            int b = base + i;
            if (b < 65536) {
#pragma unroll
                for (int r = 0; r < REP; r++) g_shist[r * 65536 + b] = 0u;
            }
        }
        if (tid == 0) g_part[bid] = 0u;
    }
    gsync(G);

    // ---- Phase E: threshold select (local) + cleanup + fixup ----
    {
        for (int i = tid; i < 2048; i += BLOCK) s_h[i] = g_hist2b[i];
        if (tid == 0) s_obin = 0xffffffffu;
        __syncthreads();
        float thr = __int_as_float(0x7f800000);
        if (ok) {
            int nb = (int)(w < 2048u ? w : 2048u);
            bsel(s_h, nb, rank2, &s_obin, &s_orank, s_wofs);
            if (s_obin == 0xffffffffu) ok = 0u;
            else thr = key2f(b2base + s_obin);
        }
        gsync(G);
        // cleanup (everyone staged what they need)
        for (int i = bid * BLOCK + tid; i < 2048; i += gstride) {
            g_hist2048[i] = 0u;
            g_hist2b[i] = 0u;
        }
        if (bid == 0 && tid == 0) {
            g_below = 0u; g_count = 0u; g_overflow = 0u;
            if (!ok) g_fail = 1u;
            else g_threshold = thr;
        }
        if (ok) {
            for (unsigned i = bid * BLOCK + tid; i < nc; i += (unsigned)gstride)
                if (key2f(g_cand[i]) >= thr) out[g_cidx[i]] = 1.0f;
        }
    }
}

// ---------------- fallback: exact 2-pass 16-bit radix, one block ------------
__global__ void f_all(const float* __restrict__ x, int n, unsigned idx) {
    if (!g_fail) return;
    __shared__ unsigned s_part[1024];
    __shared__ int s_seg;
    __shared__ unsigned s_segexcl, s_fb, s_fr;
    int tid = threadIdx.x;
    for (int b = tid; b < 65536; b += 1024) g_hist64k[b] = 0u;
    __syncthreads();
    for (int i = tid; i < n; i += blockDim.x)
        atomicAdd(&g_hist64k[f2key(x[i]) >> 16], 1u);
    __syncthreads();
    for (int phase = 0; phase < 2; phase++) {
        unsigned target = (phase == 0) ? idx : s_fr;
        if (tid == 0) s_seg = -1;
        unsigned my = 0u;
        for (int b = tid * 64; b < tid * 64 + 64; b++) my += g_hist64k[b];
        s_part[tid] = my;
        __syncthreads();
        for (int off = 1; off < 1024; off <<= 1) {
            unsigned t = (tid >= off) ? s_part[tid - off] : 0u;
            __syncthreads();
            s_part[tid] += t;
            __syncthreads();
        }
        unsigned incl = s_part[tid], excl = incl - my;
        if (my && target >= excl && target < incl) { s_seg = tid; s_segexcl = excl; }
        __syncthreads();
        if (tid == 0 && s_seg >= 0) {
            unsigned cum = s_segexcl;
            for (int b = s_seg * 64; b < s_seg * 64 + 64; b++) {
                unsigned c = g_hist64k[b];
                if (target >= cum && target < cum + c) {
                    if (phase == 0) { s_fb = (unsigned)b; s_fr = target - cum; }
                    else g_threshold = key2f((s_fb << 16) | (unsigned)b);
                    break;
                }
                cum += c;
            }
        }
        __syncthreads();
        for (int b = tid; b < 65536; b += 1024) g_hist64k[b] = 0u;
        __syncthreads();
        if (phase == 0) {
            unsigned fb = s_fb;
            for (int i = tid; i < n; i += blockDim.x) {
                unsigned key = f2key(x[i]);
                if ((key >> 16) == fb) atomicAdd(&g_hist64k[key & 0xffffu], 1u);
            }
            __syncthreads();
        }
    }
}

__global__ void f_mask(const float* __restrict__ x, float* __restrict__ out, int n) {
    if (!g_fail) return;
    const float thr = g_threshold;
    const int stride = gridDim.x * blockDim.x;
    for (int i = blockIdx.x * blockDim.x + threadIdx.x; i < n; i += stride)
        out[i] = (x[i] >= thr) ? 1.0f : 0.0f;
}

__global__ void k_fill0(float* __restrict__ out, int n) {
    const int stride = gridDim.x * blockDim.x;
    for (int i = blockIdx.x * blockDim.x + threadIdx.x; i < n; i += stride)
        out[i] = 0.0f;
}

extern "C" void kernel_launch(void* const* d_in, const int* in_sizes, int n_in,
                              void* d_out, int out_size) {
    const float* x = (const float*)d_in[0];
    float* out = (float*)d_out;
    const long long n = (long long)in_sizes[0];
    const long long k = (long long)((double)n * 0.9);
    if (k <= 0) { k_fill0<<<1184, 256>>>(out, (int)n); return; }
    const unsigned idx = (unsigned)(n - k);   // 0-indexed ascending rank
    const int n4 = (int)(n >> 2);
    const int S4 = (n4 + 31) / 32;
    const long long m = (long long)S4 * 4;
    unsigned t_target = 0u;
    if (m > 0) {
        t_target = (unsigned)((double)idx * (double)m / (double)n);
        if (t_target >= (unsigned)m) t_target = (unsigned)m - 1u;
    }

    int sm = 148, occ = 6, dev = 0;
    cudaGetDevice(&dev);
    cudaDeviceGetAttribute(&sm, cudaDevAttrMultiProcessorCount, dev);
    cudaOccupancyMaxActiveBlocksPerMultiprocessor(&occ, k_fused, BLOCK, 0);
    if (occ > 6) occ = 6;
    if (occ < 1) occ = 1;
    int G = sm * occ;
    if (G > MAXG) G = MAXG;
    if (G < 1) G = 1;

    k_fused<<<G, BLOCK>>>((const float4*)x, n4, x, (int)n, out, idx, t_target, G);
    // fallback (no-ops unless g_fail)
    f_all<<<1, 1024>>>(x, (int)n, idx);
    f_mask<<<1184, 256>>>(x, out, (int)n);
}